// round 6
// baseline (speedup 1.0000x reference)
#include <cuda_runtime.h>
#include <cuda_bf16.h>
#include <stdint.h>

// Fixed problem shape: bs=16, nq=900, nc=91, T=1600
#define NQTOT 14400
#define NCLS  91
#define TTOT  1600

#define TILE_N 32
#define TILE_T 64
#define NTH    256

// Transposed focal-cost table: tabT[c*NQTOT + n] = 2*(pos-neg) + 2
__device__ float g_tabT[NCLS * NQTOT];   // 5.24 MB, L2-resident

// ---------------------------------------------------------------------------
// Kernel A: focal class cost, written transposed via shared-memory transpose.
//   p = sigmoid(x);  -log(p) = log(1+e^-x);  -log(1-p) = x + log(1+e^-x)
// (eps=1e-8 dropped: p,1-p >= ~2e-3 for N(0,1) logits -> error << tolerance)
// ---------------------------------------------------------------------------
__global__ __launch_bounds__(1024)
void cls_table_T_kernel(const float* __restrict__ logits,
                        float* __restrict__ tabT)
{
    __shared__ float s[32][33];
    const int n = blockIdx.x * 32 + threadIdx.y;
    const int c = blockIdx.y * 32 + threadIdx.x;
    float v = 0.0f;
    if (c < NCLS) {
        float x   = logits[n * NCLS + c];
        float e   = __expf(-x);
        float p   = __fdividef(1.0f, 1.0f + e);
        float omp = e * p;                     // 1-p
        float nlp = __logf(1.0f + e);          // -log(p)
        float nlq = nlp + x;                   // -log(1-p)
        float pos = 0.25f * omp * omp * nlp;
        float neg = 0.75f * p * p * nlq;
        v = 2.0f * (pos - neg) + 2.0f;         // +2 folds the GIoU constant
    }
    s[threadIdx.y][threadIdx.x] = v;
    __syncthreads();
    const int c2 = blockIdx.y * 32 + threadIdx.y;
    const int n2 = blockIdx.x * 32 + threadIdx.x;
    if (c2 < NCLS) tabT[c2 * NQTOT + n2] = s[threadIdx.x][threadIdx.y];
}

// ---------------------------------------------------------------------------
// Kernel B: pairwise cost. Block tile 32 preds x 64 targets, 256 threads,
// thread = 2 rows x 4 consecutive targets.
//   C = 5*L1 + tabP[n,id] - 2*(inter/uni + uni/ae)     (tabP includes +2)
// ---------------------------------------------------------------------------
__global__ __launch_bounds__(NTH)
void pair_cost_kernel(const float4* __restrict__ pboxes,   // [NQTOT] cxcywh
                      const float4* __restrict__ tboxes,   // [TTOT]  cxcywh
                      const int*    __restrict__ tids,     // [TTOT]
                      const float*  __restrict__ tabT,     // [NCLS][NQTOT]
                      float*        __restrict__ out)      // [NQTOT][TTOT]
{
    __shared__ float4 s_tc[TILE_T];

    const int t0  = blockIdx.x * TILE_T;
    const int n0  = blockIdx.y * TILE_N;
    const int tid = threadIdx.x;

    if (tid < TILE_T) s_tc[tid] = tboxes[t0 + tid];

    const int txg   = tid & 15;        // target group (4 consecutive targets)
    const int nyg   = tid >> 4;        // 0..15 -> 2 rows each
    const int nr    = n0 + nyg * 2;
    const int tbase = t0 + txg * 4;

    // class costs: 2 contiguous rows per target id, straight from L2
    float2 cls[4];
    #pragma unroll
    for (int j = 0; j < 4; j++) {
        const int id = __ldg(tids + tbase + j);
        cls[j] = *reinterpret_cast<const float2*>(tabT + (size_t)id * NQTOT + nr);
    }

    // two prediction rows in registers
    const float4 c0 = pboxes[nr];
    const float4 c1 = pboxes[nr + 1];
    float4 x0, x1;
    { float hw = 0.5f * c0.z, hh = 0.5f * c0.w;
      x0 = make_float4(c0.x - hw, c0.y - hh, c0.x + hw, c0.y + hh); }
    { float hw = 0.5f * c1.z, hh = 0.5f * c1.w;
      x1 = make_float4(c1.x - hw, c1.y - hh, c1.x + hw, c1.y + hh); }
    const float a0 = c0.z * c0.w;
    const float a1 = c1.z * c1.w;

    __syncthreads();

    float r0[4], r1[4];
    #pragma unroll
    for (int j = 0; j < 4; j++) {
        const float4 tc = s_tc[(txg << 2) + j];
        const float thw = 0.5f * tc.z, thh = 0.5f * tc.w;
        const float tlx = tc.x - thw, tly = tc.y - thh;
        const float trx = tc.x + thw, tty = tc.y + thh;
        const float ta  = tc.z * tc.w;

        // ---- row 0 ----
        {
            float l1 = fabsf(c0.x - tc.x) + fabsf(c0.y - tc.y)
                     + fabsf(c0.z - tc.z) + fabsf(c0.w - tc.w);
            float ilx = fmaxf(x0.x, tlx), ily = fmaxf(x0.y, tly);
            float irx = fminf(x0.z, trx), iry = fminf(x0.w, tty);
            float wi = fmaxf(irx - ilx, 0.0f);
            float hi = fmaxf(iry - ily, 0.0f);
            float inter = wi * hi;
            float uni = a0 + ta - inter;
            float ew = fmaxf(x0.z, trx) - fminf(x0.x, tlx);
            float eh = fmaxf(x0.w, tty) - fminf(x0.y, tly);
            float ae = ew * eh;
            float q = __fdividef(inter, uni) + __fdividef(uni, ae);
            r0[j] = fmaf(-2.0f, q, fmaf(5.0f, l1, cls[j].x));
        }
        // ---- row 1 ----
        {
            float l1 = fabsf(c1.x - tc.x) + fabsf(c1.y - tc.y)
                     + fabsf(c1.z - tc.z) + fabsf(c1.w - tc.w);
            float ilx = fmaxf(x1.x, tlx), ily = fmaxf(x1.y, tly);
            float irx = fminf(x1.z, trx), iry = fminf(x1.w, tty);
            float wi = fmaxf(irx - ilx, 0.0f);
            float hi = fmaxf(iry - ily, 0.0f);
            float inter = wi * hi;
            float uni = a1 + ta - inter;
            float ew = fmaxf(x1.z, trx) - fminf(x1.x, tlx);
            float eh = fmaxf(x1.w, tty) - fminf(x1.y, tly);
            float ae = ew * eh;
            float q = __fdividef(inter, uni) + __fdividef(uni, ae);
            r1[j] = fmaf(-2.0f, q, fmaf(5.0f, l1, cls[j].y));
        }
    }

    float* orow = out + (size_t)nr * TTOT + tbase;
    *reinterpret_cast<float4*>(orow)        = make_float4(r0[0], r0[1], r0[2], r0[3]);
    *reinterpret_cast<float4*>(orow + TTOT) = make_float4(r1[0], r1[1], r1[2], r1[3]);
}

// ---------------------------------------------------------------------------
extern "C" void kernel_launch(void* const* d_in, const int* in_sizes, int n_in,
                              void* d_out, int out_size)
{
    const float* pred_logits = (const float*)d_in[0];  // [16,900,91]
    const float* pred_boxes  = (const float*)d_in[1];  // [16,900,4]
    const int*   tgt_ids     = (const int*)  d_in[2];  // [1600]
    const float* tgt_bbox    = (const float*)d_in[3];  // [1600,4]
    float*       out         = (float*)d_out;          // [16,900,1600]

    float* tabT = nullptr;
    cudaGetSymbolAddress((void**)&tabT, g_tabT);

    dim3 gA(NQTOT / 32, (NCLS + 31) / 32);             // (450, 3)
    cls_table_T_kernel<<<gA, dim3(32, 32)>>>(pred_logits, tabT);

    dim3 gB(TTOT / TILE_T, NQTOT / TILE_N);            // (25, 450)
    pair_cost_kernel<<<gB, NTH>>>(
        reinterpret_cast<const float4*>(pred_boxes),
        reinterpret_cast<const float4*>(tgt_bbox),
        tgt_ids, tabT, out);
}